// round 12
// baseline (speedup 1.0000x reference)
#include <cuda_runtime.h>
#include <cuda_fp16.h>
#include <math.h>

#define B     64
#define T     512
#define NSTEP 128
#define S     512
#define H2D   512
#define ATT   128
#define NCLS  64
#define GRID  148
#define NTH   512

// ---------------- scratch (static device globals; no allocation) ----------------
__device__ __half g_psi16[B * ATT * T];      // TRANSPOSED fp16: [b][a][tt]
__device__ __half g_h16[B * T * H2D];        // fp16 copy of h
__device__ __half g_Wphi16[ATT * S];
__device__ __half g_Wcd16[NCLS * (S + H2D)];
__device__ float  g_part[24 * 64 * 2048];    // [(slot*64+b)*2048 + row]
__device__ float  g_alpha[B * T];            // normalized attention weights
__device__ float  g_ctxp[B * 2 * H2D];       // ctx partials (2 halves per batch)
__device__ __half g_h1[B * S];
__device__ __half g_h2[B * S];
__device__ __half g_ctx[B * H2D];
__device__ float  g_c1[B * S];
__device__ float  g_c2[B * S];
__device__ unsigned g_cnt1[8];
__device__ unsigned g_cnt2;
__device__ volatile unsigned g_epoch;

__device__ __forceinline__ float tanh_fast(float v)
{
    float r;
    asm("tanh.approx.f32 %0, %1;" : "=f"(r) : "f"(v));
    return r;
}
__device__ __forceinline__ float sigf(float v) { return 0.5f * tanh_fast(0.5f * v) + 0.5f; }

// -------- two-level grid barrier (148 co-resident CTAs) ------------------------
__device__ __forceinline__ void gbar(unsigned& phase, int cta)
{
    __syncthreads();
    if (threadIdx.x == 0) {
        ++phase;
        __threadfence();
        int grp = cta & 7;
        unsigned gsz = 18u + (grp < 4 ? 1u : 0u);   // 148 = 4*19 + 4*18
        if (atomicAdd(&g_cnt1[grp], 1u) == gsz - 1u) {
            g_cnt1[grp] = 0u;
            __threadfence();
            if (atomicAdd(&g_cnt2, 1u) == 7u) {
                g_cnt2 = 0u;
                __threadfence();
                g_epoch = phase;
            } else {
                while (g_epoch != phase) {}
            }
        } else {
            while (g_epoch != phase) {}
        }
        __threadfence();
    }
    __syncthreads();
}

// ---------------- smem ----------------
struct SmAttn {
    __align__(16) float part[16][520];
    __align__(16) float vec[1024];
    __align__(16) float phi[ATT];
    __align__(16) float al[T];
    __align__(16) float red[40];
};
struct SmAll {
    __align__(16) __half Whh0s[128 * 136];  // cta 64-127: J2 slice [row][K128+8]
    __align__(16) __half Whh1s[128 * 136];  // cta 64-127: J4 slice
    __align__(16) __half Wih0s[128 * 72];   // all 128: J1 slice [row][K64+8]
    __align__(16) __half Wih1s[128 * 72];   // all 128: J3 slice
    union { __align__(16) __half As[64 * 136]; SmAttn a; } u;
};

// -------- tensor-core GEMM: D[64 b][128 rows] += A[64 b][KT] * W[128 rows][KT] --
template<int KT>
__device__ __forceinline__ void mma_gemm(const __half* __restrict__ Wsm,
        __half* __restrict__ Asm, int tid, int rowBase, int slot,
        const __half* __restrict__ z, int koff)
{
    constexpr int PK = KT + 8;

    if (KT == 128) {
        int b = tid >> 3, kq = (tid & 7) * 16;
        const uint4* src = (const uint4*)(z + b * 512 + koff + kq);
        *(uint4*)&Asm[b * PK + kq]     = src[0];
        *(uint4*)&Asm[b * PK + kq + 8] = src[1];
    } else {
        int b = tid >> 3, kq = (tid & 7) * 8;
        *(uint4*)&Asm[b * PK + kq] = *(const uint4*)(z + b * 512 + koff + kq);
    }
    __syncthreads();

    int T32 = tid & 31, w = tid >> 5;
    int tq = T32 & 3, tr = T32 >> 2;
    int bBase = (w & 3) * 16;
    int rBase = (w >> 2) * 32;

    float d[4][4];
#pragma unroll
    for (int i = 0; i < 4; ++i)
#pragma unroll
        for (int j = 0; j < 4; ++j) d[i][j] = 0.f;

    const __half* Arow  = Asm + (bBase + tr) * PK;
    const __half* Arow8 = Arow + 8 * PK;

#pragma unroll
    for (int ks = 0; ks < KT / 16; ++ks) {
        int k0 = ks * 16;
        unsigned a0 = *(const unsigned*)&Arow [k0 + 2 * tq];
        unsigned a1 = *(const unsigned*)&Arow8[k0 + 2 * tq];
        unsigned a2 = *(const unsigned*)&Arow [k0 + 8 + 2 * tq];
        unsigned a3 = *(const unsigned*)&Arow8[k0 + 8 + 2 * tq];
#pragma unroll
        for (int na = 0; na < 4; ++na) {
            const __half* Brow = Wsm + (rBase + na * 8 + tr) * PK;
            unsigned b0 = *(const unsigned*)&Brow[k0 + 2 * tq];
            unsigned b1 = *(const unsigned*)&Brow[k0 + 8 + 2 * tq];
            asm volatile(
                "mma.sync.aligned.m16n8k16.row.col.f32.f16.f16.f32 "
                "{%0,%1,%2,%3}, {%4,%5,%6,%7}, {%8,%9}, {%0,%1,%2,%3};"
                : "+f"(d[na][0]), "+f"(d[na][1]), "+f"(d[na][2]), "+f"(d[na][3])
                : "r"(a0), "r"(a1), "r"(a2), "r"(a3), "r"(b0), "r"(b1));
        }
    }

    int gr0 = rowBase + rBase;
#pragma unroll
    for (int na = 0; na < 4; ++na) {
        int rcol = gr0 + na * 8 + 2 * tq;
        *(float2*)&g_part[(size_t)(slot * 64 + bBase + tr) * 2048 + rcol] =
            make_float2(d[na][0], d[na][1]);
        *(float2*)&g_part[(size_t)(slot * 64 + bBase + tr + 8) * 2048 + rcol] =
            make_float2(d[na][2], d[na][3]);
    }
}

// -------- LSTM0 epilogue WIDE: 128 CTAs = (batch, u-half); slots J1 0-7, J2 16-19
__device__ __forceinline__ void epi0(int cta, int tid,
        const float* __restrict__ Wih0,
        const float* __restrict__ bih, const float* __restrict__ bhh,
        const int* __restrict__ x, int t)
{
    if (cta >= 128) return;
    int b    = cta & 63;
    int half = cta >> 6;
    int u    = half * 256 + (tid >> 1);
    int odd  = tid & 1;
    const int sl0[6] = {0, 1, 2, 3, 4, 5};
    const int sl1[6] = {6, 7, 16, 17, 18, 19};
    const int* sl = odd ? sl1 : sl0;
    float pre[4];
#pragma unroll
    for (int g = 0; g < 4; ++g) {
        int row = g * 512 + u;
        float s = 0.f;
#pragma unroll
        for (int i = 0; i < 6; ++i)
            s += g_part[(size_t)(sl[i] * 64 + b) * 2048 + row];
        pre[g] = s;
    }
#pragma unroll
    for (int g = 0; g < 4; ++g)
        pre[g] += __shfl_xor_sync(0xffffffffu, pre[g], 1);
    if (!odd) {
        int cls = x[b * NSTEP + t];
#pragma unroll
        for (int g = 0; g < 4; ++g) {
            int row = g * 512 + u;
            pre[g] += bih[row] + bhh[row] + Wih0[(size_t)row * 576 + cls];
        }
        float co = g_c1[b * S + u];
        float cn = sigf(pre[1]) * co + sigf(pre[0]) * tanh_fast(pre[2]);
        float hn = sigf(pre[3]) * tanh_fast(cn);
        g_c1[b * S + u] = cn;
        g_h1[b * S + u] = __float2half_rn(hn);
    }
}

// -------- attnA: epi1 (slots J3 8-15, J4 20-23) + phi + e + softmax -> g_alpha --
__device__ __forceinline__ void attnA(SmAttn* a, int cta, int tid,
        const float* __restrict__ bih1, const float* __restrict__ bhh1,
        const float* __restrict__ bphi)
{
    int b    = cta;
    int wid  = tid >> 5;
    int lane = tid & 31;

    // ---- LSTM1 epilogue ----
    {
        int u = tid;
        float pre[4];
#pragma unroll
        for (int g = 0; g < 4; ++g) {
            int row = g * 512 + u;
            float s = bih1[row] + bhh1[row];
#pragma unroll
            for (int sp = 8; sp < 16; ++sp)
                s += g_part[(size_t)(sp * 64 + b) * 2048 + row];
#pragma unroll
            for (int sp = 20; sp < 24; ++sp)
                s += g_part[(size_t)(sp * 64 + b) * 2048 + row];
            pre[g] = s;
        }
        float co = g_c2[b * S + u];
        float cn = sigf(pre[1]) * co + sigf(pre[0]) * tanh_fast(pre[2]);
        float hn = sigf(pre[3]) * tanh_fast(cn);
        g_c2[b * S + u] = cn;
        g_h2[b * S + u] = __float2half_rn(hn);
        a->vec[u] = hn;
    }
    __syncthreads();

    // ---- phi = Wphi16 @ h2 + bphi ----
#pragma unroll
    for (int i = 0; i < 8; ++i) {
        int aa = wid * 8 + i;
        const __half* wr = g_Wphi16 + aa * S;
        float sum = 0.f;
#pragma unroll
        for (int it = 0; it < 2; ++it) {
            int idx = it * 256 + lane * 8;
            uint4 w = *(const uint4*)&wr[idx];
            const __half2* wp = (const __half2*)&w;
            float4 v0 = *(const float4*)&a->vec[idx];
            float4 v1 = *(const float4*)&a->vec[idx + 4];
            float2 f0 = __half22float2(wp[0]);
            float2 f1 = __half22float2(wp[1]);
            float2 f2 = __half22float2(wp[2]);
            float2 f3 = __half22float2(wp[3]);
            sum = fmaf(f0.x, v0.x, sum); sum = fmaf(f0.y, v0.y, sum);
            sum = fmaf(f1.x, v0.z, sum); sum = fmaf(f1.y, v0.w, sum);
            sum = fmaf(f2.x, v1.x, sum); sum = fmaf(f2.y, v1.y, sum);
            sum = fmaf(f3.x, v1.z, sum); sum = fmaf(f3.y, v1.w, sum);
        }
#pragma unroll
        for (int o = 16; o > 0; o >>= 1) sum += __shfl_xor_sync(0xffffffffu, sum, o);
        if (lane == 0) a->phi[aa] = sum + bphi[aa];
    }
    __syncthreads();

    // ---- e[tt] via fp16 transposed psi ----
    {
        int aw = tid >> 6;
        int q  = tid & 63;
        const __half* pb = g_psi16 + ((size_t)b * ATT + aw * 16) * T + q * 8;
        float acc[8];
#pragma unroll
        for (int i = 0; i < 8; ++i) acc[i] = 0.f;
#pragma unroll 4
        for (int ai = 0; ai < 16; ++ai) {
            float pa = a->phi[aw * 16 + ai];
            uint4 u = *(const uint4*)&pb[(size_t)ai * T];
            const __half2* hp = (const __half2*)&u;
#pragma unroll
            for (int j = 0; j < 4; ++j) {
                float2 f = __half22float2(hp[j]);
                acc[j * 2 + 0] = fmaf(pa, f.x, acc[j * 2 + 0]);
                acc[j * 2 + 1] = fmaf(pa, f.y, acc[j * 2 + 1]);
            }
        }
        *(float4*)&a->part[aw][q * 8]     = make_float4(acc[0], acc[1], acc[2], acc[3]);
        *(float4*)&a->part[aw][q * 8 + 4] = make_float4(acc[4], acc[5], acc[6], acc[7]);
    }
    __syncthreads();

    // ---- softmax -> normalized alpha to global ----
    float e = 0.f;
#pragma unroll
    for (int r = 0; r < 8; ++r) e += a->part[r][tid];
    float m = e;
#pragma unroll
    for (int o = 16; o > 0; o >>= 1) m = fmaxf(m, __shfl_xor_sync(0xffffffffu, m, o));
    if (lane == 0) a->red[wid] = m;
    __syncthreads();
    if (tid == 0) {
        float mm = a->red[0];
        for (int i = 1; i < 16; ++i) mm = fmaxf(mm, a->red[i]);
        a->red[16] = mm;
    }
    __syncthreads();
    m = a->red[16];
    float ex = __expf(e - m);
    float ssum = ex;
#pragma unroll
    for (int o = 16; o > 0; o >>= 1) ssum += __shfl_xor_sync(0xffffffffu, ssum, o);
    if (lane == 0) a->red[wid] = ssum;
    __syncthreads();
    if (tid == 0) {
        float s = 0.f;
        for (int i = 0; i < 16; ++i) s += a->red[i];
        a->red[17] = 1.f / s;
    }
    __syncthreads();
    g_alpha[b * T + tid] = ex * a->red[17];
    __syncthreads();
}

// -------- ctxPart: 128 CTAs = (b, half): partial ctx over 256 timesteps ---------
__device__ __forceinline__ void ctxPart(SmAttn* a, int cta, int tid)
{
    int b    = cta >> 1;
    int half = cta & 1;
    int wid  = tid >> 5;
    int lane = tid & 31;

    if (tid < 256) a->al[tid] = g_alpha[b * T + half * 256 + tid];
    __syncthreads();

    const __half* hb = g_h16 + ((size_t)b * T + half * 256) * H2D;
    float acc[16];
#pragma unroll
    for (int i = 0; i < 16; ++i) acc[i] = 0.f;
#pragma unroll 4
    for (int tt = wid * 16; tt < wid * 16 + 16; ++tt) {
        float av = a->al[tt];
        const __half* hr = hb + (size_t)tt * H2D + lane * 8;
        uint4 u0 = *(const uint4*)hr;
        uint4 u1 = *(const uint4*)(hr + 256);
        const __half2* p0 = (const __half2*)&u0;
        const __half2* p1 = (const __half2*)&u1;
#pragma unroll
        for (int j = 0; j < 4; ++j) {
            float2 f0 = __half22float2(p0[j]);
            float2 f1 = __half22float2(p1[j]);
            acc[j * 2 + 0] = fmaf(av, f0.x, acc[j * 2 + 0]);
            acc[j * 2 + 1] = fmaf(av, f0.y, acc[j * 2 + 1]);
            acc[8 + j * 2 + 0] = fmaf(av, f1.x, acc[8 + j * 2 + 0]);
            acc[8 + j * 2 + 1] = fmaf(av, f1.y, acc[8 + j * 2 + 1]);
        }
    }
#pragma unroll
    for (int j = 0; j < 2; ++j) {
        *(float4*)&a->part[wid][j * 256 + lane * 8]     =
            make_float4(acc[j * 8 + 0], acc[j * 8 + 1], acc[j * 8 + 2], acc[j * 8 + 3]);
        *(float4*)&a->part[wid][j * 256 + lane * 8 + 4] =
            make_float4(acc[j * 8 + 4], acc[j * 8 + 5], acc[j * 8 + 6], acc[j * 8 + 7]);
    }
    __syncthreads();
    {
        float cv = 0.f;
#pragma unroll
        for (int w = 0; w < 16; ++w) cv += a->part[w][tid];
        g_ctxp[(size_t)(b * 2 + half) * H2D + tid] = cv;
    }
    __syncthreads();
}

// -------- attnB: combine ctx partials + output projection -----------------------
__device__ __forceinline__ void attnB(SmAttn* a, int cta, int tid,
        const float* __restrict__ bcd, float* __restrict__ out, int t)
{
    int b    = cta;
    int wid  = tid >> 5;
    int lane = tid & 31;

    a->vec[tid] = __half2float(g_h2[b * S + tid]);
    {
        float cv = g_ctxp[(size_t)(b * 2) * H2D + tid]
                 + g_ctxp[(size_t)(b * 2 + 1) * H2D + tid];
        a->vec[S + tid] = cv;
        g_ctx[b * H2D + tid] = __float2half_rn(cv);
    }
    __syncthreads();

#pragma unroll
    for (int i = 0; i < 4; ++i) {
        int c = wid * 4 + i;
        const __half* wr = g_Wcd16 + c * (S + H2D);
        float sum = 0.f;
#pragma unroll
        for (int it = 0; it < 4; ++it) {
            int idx = it * 256 + lane * 8;
            uint4 w = *(const uint4*)&wr[idx];
            const __half2* wp = (const __half2*)&w;
            float4 v0 = *(const float4*)&a->vec[idx];
            float4 v1 = *(const float4*)&a->vec[idx + 4];
            float2 f0 = __half22float2(wp[0]);
            float2 f1 = __half22float2(wp[1]);
            float2 f2 = __half22float2(wp[2]);
            float2 f3 = __half22float2(wp[3]);
            sum = fmaf(f0.x, v0.x, sum); sum = fmaf(f0.y, v0.y, sum);
            sum = fmaf(f1.x, v0.z, sum); sum = fmaf(f1.y, v0.w, sum);
            sum = fmaf(f2.x, v1.x, sum); sum = fmaf(f2.y, v1.y, sum);
            sum = fmaf(f3.x, v1.z, sum); sum = fmaf(f3.y, v1.w, sum);
        }
#pragma unroll
        for (int o = 16; o > 0; o >>= 1) sum += __shfl_xor_sync(0xffffffffu, sum, o);
        if (lane == 0) out[((size_t)b * NSTEP + t) * NCLS + c] = sum + bcd[c];
    }
    __syncthreads();
}

// ---------------- setup kernels ----------------
__global__ void k_h16(const float* __restrict__ h)
{
    size_t i = ((size_t)blockIdx.x * 256 + threadIdx.x) * 8;
    float4 v0 = *(const float4*)&h[i];
    float4 v1 = *(const float4*)&h[i + 4];
    __half2 o[4];
    o[0] = __floats2half2_rn(v0.x, v0.y);
    o[1] = __floats2half2_rn(v0.z, v0.w);
    o[2] = __floats2half2_rn(v1.x, v1.y);
    o[3] = __floats2half2_rn(v1.z, v1.w);
    *(uint4*)&g_h16[i] = *(uint4*)o;
}

__global__ void k_cvt(const float* __restrict__ Wphi, const float* __restrict__ Wcd)
{
    int i = blockIdx.x * 256 + threadIdx.x;
    g_Wphi16[i] = __float2half_rn(Wphi[i]);
    g_Wcd16[i]  = __float2half_rn(Wcd[i]);
}

// psi precompute -> fp16 transposed [b][a][tt]
__global__ void k_psi(const float* __restrict__ h,
                      const float* __restrict__ Wpsi,
                      const float* __restrict__ bpsi)
{
    __shared__ __align__(16) float hs[32][36];
    __shared__ __align__(16) float ws[128][36];
    int b   = blockIdx.y;
    int t0  = blockIdx.x * 32;
    int tid = threadIdx.x;
    int tg  = tid & 7;
    int ag  = tid >> 3;

    float acc[16];
#pragma unroll
    for (int i = 0; i < 16; ++i) acc[i] = 0.f;

    for (int dc = 0; dc < H2D; dc += 32) {
#pragma unroll
        for (int i = 0; i < 4; ++i) {
            int lin = tid + i * 256;
            int r = lin >> 5, c = lin & 31;
            hs[r][c] = h[((size_t)b * T + t0 + r) * H2D + dc + c];
        }
#pragma unroll
        for (int i = 0; i < 16; ++i) {
            int lin = tid + i * 256;
            int r = lin >> 5, c = lin & 31;
            ws[r][c] = Wpsi[r * H2D + dc + c];
        }
        __syncthreads();
#pragma unroll
        for (int k = 0; k < 32; k += 4) {
            float4 hv[4], wv[4];
#pragma unroll
            for (int j = 0; j < 4; ++j) hv[j] = *(const float4*)&hs[tg * 4 + j][k];
#pragma unroll
            for (int j = 0; j < 4; ++j) wv[j] = *(const float4*)&ws[ag * 4 + j][k];
#pragma unroll
            for (int i = 0; i < 4; ++i)
#pragma unroll
                for (int j = 0; j < 4; ++j) {
                    acc[i * 4 + j] = fmaf(hv[i].x, wv[j].x, acc[i * 4 + j]);
                    acc[i * 4 + j] = fmaf(hv[i].y, wv[j].y, acc[i * 4 + j]);
                    acc[i * 4 + j] = fmaf(hv[i].z, wv[j].z, acc[i * 4 + j]);
                    acc[i * 4 + j] = fmaf(hv[i].w, wv[j].w, acc[i * 4 + j]);
                }
        }
        __syncthreads();
    }
#pragma unroll
    for (int i = 0; i < 4; ++i)
#pragma unroll
        for (int j = 0; j < 4; ++j) {
            int tt = t0 + tg * 4 + i;
            int aa = ag * 4 + j;
            g_psi16[((size_t)b * ATT + aa) * T + tt] = __float2half_rn(acc[i * 4 + j] + bpsi[aa]);
        }
}

// ---------------- persistent mega kernel ----------------
__global__ void __launch_bounds__(NTH, 1) k_mega(
        const int* __restrict__ x, const float* __restrict__ h,
        const float* __restrict__ Wih0, const float* __restrict__ Whh0,
        const float* __restrict__ bih0, const float* __restrict__ bhh0,
        const float* __restrict__ Wih1, const float* __restrict__ Whh1,
        const float* __restrict__ bih1, const float* __restrict__ bhh1,
        const float* __restrict__ bphi, const float* __restrict__ bcd,
        float* __restrict__ out)
{
    extern __shared__ char smraw[];
    SmAll* sm = (SmAll*)smraw;

    int cta = blockIdx.x;
    int tid = threadIdx.x;
    unsigned phase = 0;
    if (tid == 0) phase = g_epoch;

    int c64  = (cta < 64) ? cta : cta - 64;
    int rg4  = c64 >> 2;
    int sp4  = c64 & 3;
    int rg8  = cta >> 3;
    int sp8  = cta & 7;

    // one-time fp16 weight staging
    if (cta >= 64 && cta < 128) {
        int r = tid >> 2, kq = (tid & 3) * 32;
        const float* s0 = Whh0 + (size_t)(rg4 * 128 + r) * 512 + sp4 * 128 + kq;
        const float* s1 = Whh1 + (size_t)(rg4 * 128 + r) * 512 + sp4 * 128 + kq;
#pragma unroll
        for (int j = 0; j < 32; ++j) {
            sm->Whh0s[r * 136 + kq + j] = __float2half_rn(s0[j]);
            sm->Whh1s[r * 136 + kq + j] = __float2half_rn(s1[j]);
        }
    }
    if (cta < 128) {
        int r = tid >> 2, kq = (tid & 3) * 16;
        const float* s0 = Wih0 + (size_t)(rg8 * 128 + r) * 576 + 64 + sp8 * 64 + kq;
        const float* s1 = Wih1 + (size_t)(rg8 * 128 + r) * 512 + sp8 * 64 + kq;
#pragma unroll
        for (int j = 0; j < 16; ++j) {
            sm->Wih0s[r * 72 + kq + j] = __float2half_rn(s0[j]);
            sm->Wih1s[r * 72 + kq + j] = __float2half_rn(s1[j]);
        }
    }

    // init states + ctx = h[:,0,:]
    if (cta < B) {
        int b = cta;
        g_ctx[b * S + tid] = __float2half_rn(h[(size_t)b * T * H2D + tid]);
        g_h1[b * S + tid]  = __float2half_rn(0.f);
        g_h2[b * S + tid]  = __float2half_rn(0.f);
        g_c1[b * S + tid]  = 0.f;
        g_c2[b * S + tid]  = 0.f;
    }
    gbar(phase, cta);

    for (int t = 0; t < NSTEP; ++t) {
        // P1: attnA[t-1] (0-63) || J2[t] = Whh0 @ h1[t-1] (64-127), slots 16-19
        if (cta >= 64 && cta < 128) {
            mma_gemm<128>(sm->Whh0s, sm->u.As, tid, rg4 * 128, 16 + sp4, g_h1, sp4 * 128);
        } else if (cta < 64 && t > 0) {
            attnA(&sm->u.a, cta, tid, bih1, bhh1, bphi);
        }
        gbar(phase, cta);

        // P2: ctx partials [t-1] (128 CTAs)
        if (cta < 128 && t > 0)
            ctxPart(&sm->u.a, cta, tid);
        gbar(phase, cta);

        // P3: attnB[t-1] (0-63) || J4[t] = Whh1 @ h2[t-1] (64-127), slots 20-23
        if (cta >= 64 && cta < 128) {
            mma_gemm<128>(sm->Whh1s, sm->u.As, tid, rg4 * 128, 20 + sp4, g_h2, sp4 * 128);
        } else if (cta < 64 && t > 0) {
            attnB(&sm->u.a, cta, tid, bcd, out, t - 1);
        }
        gbar(phase, cta);

        // P4: J1[t] = Wih0 @ ctx[t-1] (128 CTAs, K=64), slots 0-7
        if (cta < 128)
            mma_gemm<64>(sm->Wih0s, sm->u.As, tid, rg8 * 128, sp8, g_ctx, sp8 * 64);
        gbar(phase, cta);

        // P5: epi0[t] -> h1[t] (128 CTAs)
        epi0(cta, tid, Wih0, bih0, bhh0, x, t);
        gbar(phase, cta);

        // P6: J3[t] = Wih1 @ h1[t] (128 CTAs, K=64), slots 8-15
        if (cta < 128)
            mma_gemm<64>(sm->Wih1s, sm->u.As, tid, rg8 * 128, 8 + sp8, g_h1, sp8 * 64);
        gbar(phase, cta);
    }

    // tail: attention for the final step
    if (cta < 64)
        attnA(&sm->u.a, cta, tid, bih1, bhh1, bphi);
    gbar(phase, cta);
    if (cta < 128)
        ctxPart(&sm->u.a, cta, tid);
    gbar(phase, cta);
    if (cta < 64)
        attnB(&sm->u.a, cta, tid, bcd, out, NSTEP - 1);
}

// ---------------- launcher ----------------
extern "C" void kernel_launch(void* const* d_in, const int* in_sizes, int n_in,
                              void* d_out, int out_size)
{
    const int*   x    = (const int*)d_in[0];
    const float* h    = (const float*)d_in[1];
    const float* Wih0 = (const float*)d_in[2];
    const float* Whh0 = (const float*)d_in[3];
    const float* bih0 = (const float*)d_in[4];
    const float* bhh0 = (const float*)d_in[5];
    const float* Wih1 = (const float*)d_in[6];
    const float* Whh1 = (const float*)d_in[7];
    const float* bih1 = (const float*)d_in[8];
    const float* bhh1 = (const float*)d_in[9];
    const float* Wphi = (const float*)d_in[10];
    const float* bphi = (const float*)d_in[11];
    const float* Wpsi = (const float*)d_in[12];
    const float* bpsi = (const float*)d_in[13];
    const float* Wcd  = (const float*)d_in[14];
    const float* bcd  = (const float*)d_in[15];
    float* out = (float*)d_out;

    static int smem_set = 0;
    if (!smem_set) {
        cudaFuncSetAttribute(k_mega, cudaFuncAttributeMaxDynamicSharedMemorySize,
                             (int)sizeof(SmAll));
        smem_set = 1;
    }

    k_h16<<<(B * T * H2D) / (256 * 8), 256>>>(h);
    k_cvt<<<(ATT * S) / 256, 256>>>(Wphi, Wcd);
    k_psi<<<dim3(T / 32, B), 256>>>(h, Wpsi, bpsi);
    k_mega<<<GRID, NTH, sizeof(SmAll)>>>(x, h, Wih0, Whh0, bih0, bhh0,
                                         Wih1, Whh1, bih1, bhh1,
                                         bphi, bcd, out);
}

// round 13
// speedup vs baseline: 1.1033x; 1.1033x over previous
#include <cuda_runtime.h>
#include <cuda_fp16.h>
#include <math.h>

#define B     64
#define T     512
#define NSTEP 128
#define S     512
#define H2D   512
#define ATT   128
#define NCLS  64
#define GRID  148
#define NTH   512

// ---------------- scratch (static device globals; no allocation) ----------------
__device__ __half g_psi16[B * ATT * T];      // TRANSPOSED fp16: [b][a][tt]
__device__ __half g_h16[B * T * H2D];        // fp16 copy of h
__device__ __half g_Wphi16[ATT * S];
__device__ __half g_Wcd16[NCLS * (S + H2D)];
__device__ float  g_part[20 * 64 * 2048];    // [(slot*64+b)*2048 + row]
__device__ float  g_alpha[B * 256];          // alpha for tt 256..511 (helper half)
__device__ float  g_ctxp[B * H2D];           // helper's ctx partial
__device__ __half g_h1[B * S];
__device__ __half g_h2[B * S];
__device__ __half g_ctx[B * H2D];
__device__ float  g_c1[B * S];
__device__ float  g_c2[B * S];
__device__ volatile unsigned g_flagA[64];
__device__ volatile unsigned g_flagB[64];
__device__ unsigned g_cnt1[8];
__device__ unsigned g_cnt2;
__device__ volatile unsigned g_epoch;

__device__ __forceinline__ float tanh_fast(float v)
{
    float r;
    asm("tanh.approx.f32 %0, %1;" : "=f"(r) : "f"(v));
    return r;
}
__device__ __forceinline__ float sigf(float v) { return 0.5f * tanh_fast(0.5f * v) + 0.5f; }

// -------- two-level grid barrier (148 co-resident CTAs) ------------------------
__device__ __forceinline__ void gbar(unsigned& phase, int cta)
{
    __syncthreads();
    if (threadIdx.x == 0) {
        ++phase;
        __threadfence();
        int grp = cta & 7;
        unsigned gsz = 18u + (grp < 4 ? 1u : 0u);   // 148 = 4*19 + 4*18
        if (atomicAdd(&g_cnt1[grp], 1u) == gsz - 1u) {
            g_cnt1[grp] = 0u;
            __threadfence();
            if (atomicAdd(&g_cnt2, 1u) == 7u) {
                g_cnt2 = 0u;
                __threadfence();
                g_epoch = phase;
            } else {
                while (g_epoch != phase) {}
            }
        } else {
            while (g_epoch != phase) {}
        }
        __threadfence();
    }
    __syncthreads();
}

// ---------------- smem ----------------
struct SmAttn {
    __align__(16) float part[16][520];
    __align__(16) float vec[1024];
    __align__(16) float phi[ATT];
    __align__(16) float al[T];
    __align__(16) float red[40];
};
struct SmAll {
    __align__(16) __half Wa[128 * 136];   // J1 (cta<64) / J2 (cta 64-127), [row][K128+8]
    __align__(16) __half Wb[128 * 136];   // J4 (cta 64-127)
    __align__(16) __half Wc[128 * 72];    // J3 (all 128), [row][K64+8]
    union { __align__(16) __half As[64 * 136]; SmAttn a; } u;
};

// -------- tensor-core GEMM: D[64 b][128 rows] += A[64 b][KT] * W[128 rows][KT] --
template<int KT>
__device__ __forceinline__ void mma_gemm(const __half* __restrict__ Wsm,
        __half* __restrict__ Asm, int tid, int rowBase, int slot,
        const __half* __restrict__ z, int koff)
{
    constexpr int PK = KT + 8;

    if (KT == 128) {
        int b = tid >> 3, kq = (tid & 7) * 16;
        const uint4* src = (const uint4*)(z + b * 512 + koff + kq);
        *(uint4*)&Asm[b * PK + kq]     = src[0];
        *(uint4*)&Asm[b * PK + kq + 8] = src[1];
    } else {
        int b = tid >> 3, kq = (tid & 7) * 8;
        *(uint4*)&Asm[b * PK + kq] = *(const uint4*)(z + b * 512 + koff + kq);
    }
    __syncthreads();

    int T32 = tid & 31, w = tid >> 5;
    int tq = T32 & 3, tr = T32 >> 2;
    int bBase = (w & 3) * 16;
    int rBase = (w >> 2) * 32;

    float d[4][4];
#pragma unroll
    for (int i = 0; i < 4; ++i)
#pragma unroll
        for (int j = 0; j < 4; ++j) d[i][j] = 0.f;

    const __half* Arow  = Asm + (bBase + tr) * PK;
    const __half* Arow8 = Arow + 8 * PK;

#pragma unroll
    for (int ks = 0; ks < KT / 16; ++ks) {
        int k0 = ks * 16;
        unsigned a0 = *(const unsigned*)&Arow [k0 + 2 * tq];
        unsigned a1 = *(const unsigned*)&Arow8[k0 + 2 * tq];
        unsigned a2 = *(const unsigned*)&Arow [k0 + 8 + 2 * tq];
        unsigned a3 = *(const unsigned*)&Arow8[k0 + 8 + 2 * tq];
#pragma unroll
        for (int na = 0; na < 4; ++na) {
            const __half* Brow = Wsm + (rBase + na * 8 + tr) * PK;
            unsigned b0 = *(const unsigned*)&Brow[k0 + 2 * tq];
            unsigned b1 = *(const unsigned*)&Brow[k0 + 8 + 2 * tq];
            asm volatile(
                "mma.sync.aligned.m16n8k16.row.col.f32.f16.f16.f32 "
                "{%0,%1,%2,%3}, {%4,%5,%6,%7}, {%8,%9}, {%0,%1,%2,%3};"
                : "+f"(d[na][0]), "+f"(d[na][1]), "+f"(d[na][2]), "+f"(d[na][3])
                : "r"(a0), "r"(a1), "r"(a2), "r"(a3), "r"(b0), "r"(b1));
        }
    }

    int gr0 = rowBase + rBase;
#pragma unroll
    for (int na = 0; na < 4; ++na) {
        int rcol = gr0 + na * 8 + 2 * tq;
        *(float2*)&g_part[(size_t)(slot * 64 + bBase + tr) * 2048 + rcol] =
            make_float2(d[na][0], d[na][1]);
        *(float2*)&g_part[(size_t)(slot * 64 + bBase + tr + 8) * 2048 + rcol] =
            make_float2(d[na][2], d[na][3]);
    }
}

// -------- LSTM0 epilogue WIDE: 128 CTAs = (batch, u-half); slots 0-7 ------------
__device__ __forceinline__ void epi0(int cta, int tid,
        const float* __restrict__ Wih0,
        const float* __restrict__ bih, const float* __restrict__ bhh,
        const int* __restrict__ x, int t)
{
    if (cta >= 128) return;
    int b    = cta & 63;
    int half = cta >> 6;
    int u    = half * 256 + (tid >> 1);
    int sh   = (tid & 1) * 4;
    float pre[4];
#pragma unroll
    for (int g = 0; g < 4; ++g) {
        int row = g * 512 + u;
        float s = 0.f;
#pragma unroll
        for (int sp = 0; sp < 4; ++sp)
            s += g_part[(size_t)((sh + sp) * 64 + b) * 2048 + row];
        pre[g] = s;
    }
#pragma unroll
    for (int g = 0; g < 4; ++g)
        pre[g] += __shfl_xor_sync(0xffffffffu, pre[g], 1);
    if ((tid & 1) == 0) {
        int cls = x[b * NSTEP + t];
#pragma unroll
        for (int g = 0; g < 4; ++g) {
            int row = g * 512 + u;
            pre[g] += bih[row] + bhh[row] + Wih0[(size_t)row * 576 + cls];
        }
        float co = g_c1[b * S + u];
        float cn = sigf(pre[1]) * co + sigf(pre[0]) * tanh_fast(pre[2]);
        float hn = sigf(pre[3]) * tanh_fast(cn);
        g_c1[b * S + u] = cn;
        g_h1[b * S + u] = __float2half_rn(hn);
    }
}

// -------- ctx accumulation over a 256-timestep half (16 warps x 16 tt) ----------
// alpha in alsm[0..255]; result per-thread partial cv (via part[] reduce)
__device__ __forceinline__ float ctx_half(SmAttn* a, int tid,
        const __half* __restrict__ hb, const float* __restrict__ alsm)
{
    int wid  = tid >> 5;
    int lane = tid & 31;
    float acc[16];
#pragma unroll
    for (int i = 0; i < 16; ++i) acc[i] = 0.f;
#pragma unroll 4
    for (int tt = wid * 16; tt < wid * 16 + 16; ++tt) {
        float av = alsm[tt];
        const __half* hr = hb + (size_t)tt * H2D + lane * 8;
        uint4 u0 = *(const uint4*)hr;
        uint4 u1 = *(const uint4*)(hr + 256);
        const __half2* p0 = (const __half2*)&u0;
        const __half2* p1 = (const __half2*)&u1;
#pragma unroll
        for (int j = 0; j < 4; ++j) {
            float2 f0 = __half22float2(p0[j]);
            float2 f1 = __half22float2(p1[j]);
            acc[j * 2 + 0] = fmaf(av, f0.x, acc[j * 2 + 0]);
            acc[j * 2 + 1] = fmaf(av, f0.y, acc[j * 2 + 1]);
            acc[8 + j * 2 + 0] = fmaf(av, f1.x, acc[8 + j * 2 + 0]);
            acc[8 + j * 2 + 1] = fmaf(av, f1.y, acc[8 + j * 2 + 1]);
        }
    }
#pragma unroll
    for (int j = 0; j < 2; ++j) {
        *(float4*)&a->part[wid][j * 256 + lane * 8]     =
            make_float4(acc[j * 8 + 0], acc[j * 8 + 1], acc[j * 8 + 2], acc[j * 8 + 3]);
        *(float4*)&a->part[wid][j * 256 + lane * 8 + 4] =
            make_float4(acc[j * 8 + 4], acc[j * 8 + 5], acc[j * 8 + 6], acc[j * 8 + 7]);
    }
    __syncthreads();
    float cv = 0.f;
#pragma unroll
    for (int w = 0; w < 16; ++w) cv += a->part[w][tid];
    return cv;
}

// -------- attention main (CTA 0-63): epi1+phi+e+softmax, ctx half0, combine, proj
__device__ __forceinline__ void attn_main(SmAttn* a, int b, int tid,
        const float* __restrict__ bih1, const float* __restrict__ bhh1,
        const float* __restrict__ bphi, const float* __restrict__ bcd,
        float* __restrict__ out, int t)
{
    int wid  = tid >> 5;
    int lane = tid & 31;

    // ---- LSTM1 epilogue (slots 8-19) ----
    {
        int u = tid;
        float pre[4];
#pragma unroll
        for (int g = 0; g < 4; ++g) {
            int row = g * 512 + u;
            float s = bih1[row] + bhh1[row];
#pragma unroll
            for (int sp = 8; sp < 20; ++sp)
                s += g_part[(size_t)(sp * 64 + b) * 2048 + row];
            pre[g] = s;
        }
        float co = g_c2[b * S + u];
        float cn = sigf(pre[1]) * co + sigf(pre[0]) * tanh_fast(pre[2]);
        float hn = sigf(pre[3]) * tanh_fast(cn);
        g_c2[b * S + u] = cn;
        g_h2[b * S + u] = __float2half_rn(hn);
        a->vec[u] = hn;
    }
    __syncthreads();

    // ---- phi = Wphi16 @ h2 + bphi ----
#pragma unroll
    for (int i = 0; i < 8; ++i) {
        int aa = wid * 8 + i;
        const __half* wr = g_Wphi16 + aa * S;
        float sum = 0.f;
#pragma unroll
        for (int it = 0; it < 2; ++it) {
            int idx = it * 256 + lane * 8;
            uint4 w = *(const uint4*)&wr[idx];
            const __half2* wp = (const __half2*)&w;
            float4 v0 = *(const float4*)&a->vec[idx];
            float4 v1 = *(const float4*)&a->vec[idx + 4];
            float2 f0 = __half22float2(wp[0]);
            float2 f1 = __half22float2(wp[1]);
            float2 f2 = __half22float2(wp[2]);
            float2 f3 = __half22float2(wp[3]);
            sum = fmaf(f0.x, v0.x, sum); sum = fmaf(f0.y, v0.y, sum);
            sum = fmaf(f1.x, v0.z, sum); sum = fmaf(f1.y, v0.w, sum);
            sum = fmaf(f2.x, v1.x, sum); sum = fmaf(f2.y, v1.y, sum);
            sum = fmaf(f3.x, v1.z, sum); sum = fmaf(f3.y, v1.w, sum);
        }
#pragma unroll
        for (int o = 16; o > 0; o >>= 1) sum += __shfl_xor_sync(0xffffffffu, sum, o);
        if (lane == 0) a->phi[aa] = sum + bphi[aa];
    }
    __syncthreads();

    // ---- e[tt] via fp16 transposed psi ----
    {
        int aw = tid >> 6;
        int q  = tid & 63;
        const __half* pb = g_psi16 + ((size_t)b * ATT + aw * 16) * T + q * 8;
        float acc[8];
#pragma unroll
        for (int i = 0; i < 8; ++i) acc[i] = 0.f;
#pragma unroll 4
        for (int ai = 0; ai < 16; ++ai) {
            float pa = a->phi[aw * 16 + ai];
            uint4 u = *(const uint4*)&pb[(size_t)ai * T];
            const __half2* hp = (const __half2*)&u;
#pragma unroll
            for (int j = 0; j < 4; ++j) {
                float2 f = __half22float2(hp[j]);
                acc[j * 2 + 0] = fmaf(pa, f.x, acc[j * 2 + 0]);
                acc[j * 2 + 1] = fmaf(pa, f.y, acc[j * 2 + 1]);
            }
        }
        *(float4*)&a->part[aw][q * 8]     = make_float4(acc[0], acc[1], acc[2], acc[3]);
        *(float4*)&a->part[aw][q * 8 + 4] = make_float4(acc[4], acc[5], acc[6], acc[7]);
    }
    __syncthreads();

    // ---- softmax -> normalized alpha (local smem + helper half to global) ----
    float e = 0.f;
#pragma unroll
    for (int r = 0; r < 8; ++r) e += a->part[r][tid];
    float m = e;
#pragma unroll
    for (int o = 16; o > 0; o >>= 1) m = fmaxf(m, __shfl_xor_sync(0xffffffffu, m, o));
    if (lane == 0) a->red[wid] = m;
    __syncthreads();
    if (tid == 0) {
        float mm = a->red[0];
        for (int i = 1; i < 16; ++i) mm = fmaxf(mm, a->red[i]);
        a->red[16] = mm;
    }
    __syncthreads();
    m = a->red[16];
    float ex = __expf(e - m);
    float ssum = ex;
#pragma unroll
    for (int o = 16; o > 0; o >>= 1) ssum += __shfl_xor_sync(0xffffffffu, ssum, o);
    if (lane == 0) a->red[wid] = ssum;
    __syncthreads();
    if (tid == 0) {
        float s = 0.f;
        for (int i = 0; i < 16; ++i) s += a->red[i];
        a->red[17] = 1.f / s;
    }
    __syncthreads();
    float al = ex * a->red[17];
    a->al[tid] = al;
    if (tid >= 256) g_alpha[b * 256 + (tid - 256)] = al;
    __threadfence();
    __syncthreads();
    if (tid == 0) g_flagA[b] = (unsigned)(t + 1);   // release alpha to helper

    // ---- ctx half 0 (tt 0-255) ----
    float cv0 = ctx_half(a, tid, g_h16 + (size_t)b * T * H2D, a->al);

    // ---- wait helper's half, combine ----
    if (tid == 0) { while (g_flagB[b] != (unsigned)(t + 1)) {} }
    __syncthreads();
    __threadfence();
    {
        float cv = cv0 + __ldcg(&g_ctxp[b * H2D + tid]);
        a->vec[S + tid] = cv;
        g_ctx[b * H2D + tid] = __float2half_rn(cv);
    }
    __syncthreads();

    // ---- out = Wcd16 @ [h2; ctx] + bcd ----
#pragma unroll
    for (int i = 0; i < 4; ++i) {
        int c = wid * 4 + i;
        const __half* wr = g_Wcd16 + c * (S + H2D);
        float sum = 0.f;
#pragma unroll
        for (int it = 0; it < 4; ++it) {
            int idx = it * 256 + lane * 8;
            uint4 w = *(const uint4*)&wr[idx];
            const __half2* wp = (const __half2*)&w;
            float4 v0 = *(const float4*)&a->vec[idx];
            float4 v1 = *(const float4*)&a->vec[idx + 4];
            float2 f0 = __half22float2(wp[0]);
            float2 f1 = __half22float2(wp[1]);
            float2 f2 = __half22float2(wp[2]);
            float2 f3 = __half22float2(wp[3]);
            sum = fmaf(f0.x, v0.x, sum); sum = fmaf(f0.y, v0.y, sum);
            sum = fmaf(f1.x, v0.z, sum); sum = fmaf(f1.y, v0.w, sum);
            sum = fmaf(f2.x, v1.x, sum); sum = fmaf(f2.y, v1.y, sum);
            sum = fmaf(f3.x, v1.z, sum); sum = fmaf(f3.y, v1.w, sum);
        }
#pragma unroll
        for (int o = 16; o > 0; o >>= 1) sum += __shfl_xor_sync(0xffffffffu, sum, o);
        if (lane == 0) out[((size_t)b * NSTEP + t) * NCLS + c] = sum + bcd[c];
    }
    __syncthreads();
}

// -------- ctx helper (CTA 64-127): wait alpha, stream tt 256-511, publish -------
__device__ __forceinline__ void ctx_helper(SmAttn* a, int b, int tid, int t)
{
    if (tid == 0) { while (g_flagA[b] != (unsigned)(t + 1)) {} }
    __syncthreads();
    __threadfence();
    if (tid < 256) a->al[tid] = __ldcg(&g_alpha[b * 256 + tid]);
    __syncthreads();

    float cv1 = ctx_half(a, tid, g_h16 + ((size_t)b * T + 256) * H2D, a->al);
    g_ctxp[b * H2D + tid] = cv1;
    __threadfence();
    __syncthreads();
    if (tid == 0) g_flagB[b] = (unsigned)(t + 1);
    __syncthreads();
}

// ---------------- setup kernels ----------------
__global__ void k_h16(const float* __restrict__ h)
{
    size_t i = ((size_t)blockIdx.x * 256 + threadIdx.x) * 8;
    float4 v0 = *(const float4*)&h[i];
    float4 v1 = *(const float4*)&h[i + 4];
    __half2 o[4];
    o[0] = __floats2half2_rn(v0.x, v0.y);
    o[1] = __floats2half2_rn(v0.z, v0.w);
    o[2] = __floats2half2_rn(v1.x, v1.y);
    o[3] = __floats2half2_rn(v1.z, v1.w);
    *(uint4*)&g_h16[i] = *(uint4*)o;
}

__global__ void k_cvt(const float* __restrict__ Wphi, const float* __restrict__ Wcd)
{
    int i = blockIdx.x * 256 + threadIdx.x;
    g_Wphi16[i] = __float2half_rn(Wphi[i]);
    g_Wcd16[i]  = __float2half_rn(Wcd[i]);
}

// psi precompute -> fp16 transposed [b][a][tt]
__global__ void k_psi(const float* __restrict__ h,
                      const float* __restrict__ Wpsi,
                      const float* __restrict__ bpsi)
{
    __shared__ __align__(16) float hs[32][36];
    __shared__ __align__(16) float ws[128][36];
    int b   = blockIdx.y;
    int t0  = blockIdx.x * 32;
    int tid = threadIdx.x;
    int tg  = tid & 7;
    int ag  = tid >> 3;

    float acc[16];
#pragma unroll
    for (int i = 0; i < 16; ++i) acc[i] = 0.f;

    for (int dc = 0; dc < H2D; dc += 32) {
#pragma unroll
        for (int i = 0; i < 4; ++i) {
            int lin = tid + i * 256;
            int r = lin >> 5, c = lin & 31;
            hs[r][c] = h[((size_t)b * T + t0 + r) * H2D + dc + c];
        }
#pragma unroll
        for (int i = 0; i < 16; ++i) {
            int lin = tid + i * 256;
            int r = lin >> 5, c = lin & 31;
            ws[r][c] = Wpsi[r * H2D + dc + c];
        }
        __syncthreads();
#pragma unroll
        for (int k = 0; k < 32; k += 4) {
            float4 hv[4], wv[4];
#pragma unroll
            for (int j = 0; j < 4; ++j) hv[j] = *(const float4*)&hs[tg * 4 + j][k];
#pragma unroll
            for (int j = 0; j < 4; ++j) wv[j] = *(const float4*)&ws[ag * 4 + j][k];
#pragma unroll
            for (int i = 0; i < 4; ++i)
#pragma unroll
                for (int j = 0; j < 4; ++j) {
                    acc[i * 4 + j] = fmaf(hv[i].x, wv[j].x, acc[i * 4 + j]);
                    acc[i * 4 + j] = fmaf(hv[i].y, wv[j].y, acc[i * 4 + j]);
                    acc[i * 4 + j] = fmaf(hv[i].z, wv[j].z, acc[i * 4 + j]);
                    acc[i * 4 + j] = fmaf(hv[i].w, wv[j].w, acc[i * 4 + j]);
                }
        }
        __syncthreads();
    }
#pragma unroll
    for (int i = 0; i < 4; ++i)
#pragma unroll
        for (int j = 0; j < 4; ++j) {
            int tt = t0 + tg * 4 + i;
            int aa = ag * 4 + j;
            g_psi16[((size_t)b * ATT + aa) * T + tt] = __float2half_rn(acc[i * 4 + j] + bpsi[aa]);
        }
}

// ---------------- persistent mega kernel ----------------
__global__ void __launch_bounds__(NTH, 1) k_mega(
        const int* __restrict__ x, const float* __restrict__ h,
        const float* __restrict__ Wih0, const float* __restrict__ Whh0,
        const float* __restrict__ bih0, const float* __restrict__ bhh0,
        const float* __restrict__ Wih1, const float* __restrict__ Whh1,
        const float* __restrict__ bih1, const float* __restrict__ bhh1,
        const float* __restrict__ bphi, const float* __restrict__ bcd,
        float* __restrict__ out)
{
    extern __shared__ char smraw[];
    SmAll* sm = (SmAll*)smraw;

    int cta = blockIdx.x;
    int tid = threadIdx.x;
    unsigned phase = 0;
    if (tid == 0) phase = g_epoch;

    int c64  = (cta < 64) ? cta : cta - 64;
    int rg4  = c64 >> 2;
    int sp4  = c64 & 3;
    int rg8  = cta >> 3;
    int sp8  = cta & 7;

    // one-time fp16 weight staging, layout [row][K+8]
    if (cta < 64) {
        int r = tid >> 2, kq = (tid & 3) * 32;
        const float* src = Wih0 + (size_t)(rg4 * 128 + r) * 576 + 64 + sp4 * 128 + kq;
#pragma unroll
        for (int j = 0; j < 32; ++j)
            sm->Wa[r * 136 + kq + j] = __float2half_rn(src[j]);
    } else if (cta < 128) {
        int r = tid >> 2, kq = (tid & 3) * 32;
        const float* s0 = Whh0 + (size_t)(rg4 * 128 + r) * 512 + sp4 * 128 + kq;
        const float* s1 = Whh1 + (size_t)(rg4 * 128 + r) * 512 + sp4 * 128 + kq;
#pragma unroll
        for (int j = 0; j < 32; ++j) {
            sm->Wa[r * 136 + kq + j] = __float2half_rn(s0[j]);
            sm->Wb[r * 136 + kq + j] = __float2half_rn(s1[j]);
        }
    }
    if (cta < 128) {
        int r = tid >> 2, kq = (tid & 3) * 16;
        const float* src = Wih1 + (size_t)(rg8 * 128 + r) * 512 + sp8 * 64 + kq;
#pragma unroll
        for (int j = 0; j < 16; ++j)
            sm->Wc[r * 72 + kq + j] = __float2half_rn(src[j]);
    }

    // init states + ctx = h[:,0,:] + flags
    if (cta < B) {
        int b = cta;
        g_ctx[b * S + tid] = __float2half_rn(h[(size_t)b * T * H2D + tid]);
        g_h1[b * S + tid]  = __float2half_rn(0.f);
        g_h2[b * S + tid]  = __float2half_rn(0.f);
        g_c1[b * S + tid]  = 0.f;
        g_c2[b * S + tid]  = 0.f;
        if (tid == 0) { g_flagA[b] = 0u; g_flagB[b] = 0u; }
    }
    gbar(phase, cta);

    for (int t = 0; t < NSTEP; ++t) {
        // P1: [attn_main(t-1)] (0-63) || [J2(t) then ctx_helper(t-1)] (64-127)
        if (cta >= 64 && cta < 128) {
            mma_gemm<128>(sm->Wa, sm->u.As, tid, rg4 * 128, 4 + sp4, g_h1, sp4 * 128);
            if (t > 0) ctx_helper(&sm->u.a, c64, tid, t - 1);
        } else if (cta < 64 && t > 0) {
            attn_main(&sm->u.a, cta, tid, bih1, bhh1, bphi, bcd, out, t - 1);
        }
        gbar(phase, cta);

        // P2: J1 = Wih0 @ ctx[t-1] (0-63) || J4 = Whh1 @ h2[t-1] (64-127)
        if (cta < 64) {
            mma_gemm<128>(sm->Wa, sm->u.As, tid, rg4 * 128, sp4, g_ctx, sp4 * 128);
        } else if (cta < 128) {
            mma_gemm<128>(sm->Wb, sm->u.As, tid, rg4 * 128, 16 + sp4, g_h2, sp4 * 128);
        }
        gbar(phase, cta);

        // P3: epi0 (wide, 128 CTAs) -> h1[t]
        epi0(cta, tid, Wih0, bih0, bhh0, x, t);
        gbar(phase, cta);

        // P4: J3 = Wih1 @ h1[t] (128 CTAs, K=64)
        if (cta < 128) {
            mma_gemm<64>(sm->Wc, sm->u.As, tid, rg8 * 128, 8 + sp8, g_h1, sp8 * 64);
        }
        gbar(phase, cta);
    }

    // tail: attention for the final step (main + helper roles)
    if (cta < 64)
        attn_main(&sm->u.a, cta, tid, bih1, bhh1, bphi, bcd, out, NSTEP - 1);
    else if (cta < 128)
        ctx_helper(&sm->u.a, c64, tid, NSTEP - 1);
}

// ---------------- launcher ----------------
extern "C" void kernel_launch(void* const* d_in, const int* in_sizes, int n_in,
                              void* d_out, int out_size)
{
    const int*   x    = (const int*)d_in[0];
    const float* h    = (const float*)d_in[1];
    const float* Wih0 = (const float*)d_in[2];
    const float* Whh0 = (const float*)d_in[3];
    const float* bih0 = (const float*)d_in[4];
    const float* bhh0 = (const float*)d_in[5];
    const float* Wih1 = (const float*)d_in[6];
    const float* Whh1 = (const float*)d_in[7];
    const float* bih1 = (const float*)d_in[8];
    const float* bhh1 = (const float*)d_in[9];
    const float* Wphi = (const float*)d_in[10];
    const float* bphi = (const float*)d_in[11];
    const float* Wpsi = (const float*)d_in[12];
    const float* bpsi = (const float*)d_in[13];
    const float* Wcd  = (const float*)d_in[14];
    const float* bcd  = (const float*)d_in[15];
    float* out = (float*)d_out;

    static int smem_set = 0;
    if (!smem_set) {
        cudaFuncSetAttribute(k_mega, cudaFuncAttributeMaxDynamicSharedMemorySize,
                             (int)sizeof(SmAll));
        smem_set = 1;
    }

    k_h16<<<(B * T * H2D) / (256 * 8), 256>>>(h);
    k_cvt<<<(ATT * S) / 256, 256>>>(Wphi, Wcd);
    k_psi<<<dim3(T / 32, B), 256>>>(h, Wpsi, bpsi);
    k_mega<<<GRID, NTH, sizeof(SmAll)>>>(x, h, Wih0, Whh0, bih0, bhh0,
                                         Wih1, Whh1, bih1, bhh1,
                                         bphi, bcd, out);
}